// round 4
// baseline (speedup 1.0000x reference)
#include <cuda_runtime.h>
#include <cuda_bf16.h>

// Problem constants (from reference)
#define Bq 128
#define Nq 36
#define Dq 512
#define D4q 128          // Dq/4
#define Gq 2
#define NDq (Nq * Dq)
#define NEGV -1e10f

// One block per batch element, 1024 threads (32 warps).
// logits factorization:
//   logits[b,n,g] = sum_d o[n,d]^2 * SW[g,d] - sum_d o[n,d] * T[b,g,d]
//   SW[g,d] = sum_m W[g,m,d],  T[b,g,d] = sum_m W[g,m,d]*o[b,m,d]
// Phase 1 is the only DRAM-facing phase: all loads are LDG.128 (float4),
// parallelized as 256 (g,d4) columns x 4 m-slices, reduced via smem.
__global__ __launch_bounds__(1024, 1)
void qgen_attn_kernel(const float* __restrict__ obj,   // [B, N, D]
                      const float* __restrict__ W,     // [G, N*D]
                      const float* __restrict__ bias,  // [G]
                      const unsigned char* __restrict__ mask_bytes, // [B,N]
                      float* __restrict__ out)         // [B, G*D]
{
    __shared__ __align__(16) float4 swp[4][256];   // 16 KB partials
    __shared__ __align__(16) float4 tp [4][256];   // 16 KB partials
    __shared__ __align__(16) float  T_s[Gq * Dq];  // 4 KB
    __shared__ __align__(16) float  SW_s[Gq * Dq]; // 4 KB
    __shared__ float logit_s[Nq * Gq];             // 288 B
    __shared__ float weight_s[Nq * Gq];            // 288 B
    __shared__ int   nonzero_offbyte;

    const int b   = blockIdx.x;
    const int tid = threadIdx.x;      // 0..1023

    if (tid == 0) nonzero_offbyte = 0;
    __syncthreads();

    // ---- Mask dtype detection (int32 => all bytes at offset%4!=0 are zero) ----
    if (tid < 256 && (tid & 3) != 0) {
        if (mask_bytes[tid] != 0) atomicOr(&nonzero_offbyte, 1);
    }

    const float* __restrict__ objb = obj + (size_t)b * NDq;
    const float4* __restrict__ obj4 = (const float4*)objb;   // [N][D4]

    // ---- Phase 1 (DRAM): SW/T partials, all float4 ----
    {
        const int col = tid & 255;     // 0..255  (g,d4) column
        const int g1  = col >> 7;      // 0..1
        const int d4  = col & 127;     // 0..127
        const int ms  = tid >> 8;      // 0..3 m-slice (9 m's each)
        const float4* __restrict__ W4 = (const float4*)(W + (size_t)g1 * NDq);

        float4 sw = make_float4(0.f, 0.f, 0.f, 0.f);
        float4 t  = make_float4(0.f, 0.f, 0.f, 0.f);
        #pragma unroll
        for (int j = 0; j < 9; j++) {
            const int m = ms * 9 + j;
            float4 w = __ldg(W4   + m * D4q + d4);
            float4 o = __ldg(obj4 + m * D4q + d4);
            sw.x += w.x; sw.y += w.y; sw.z += w.z; sw.w += w.w;
            t.x = fmaf(w.x, o.x, t.x);
            t.y = fmaf(w.y, o.y, t.y);
            t.z = fmaf(w.z, o.z, t.z);
            t.w = fmaf(w.w, o.w, t.w);
        }
        swp[ms][col] = sw;
        tp [ms][col] = t;
    }
    __syncthreads();

    // reduce 4 m-slices -> final SW_s / T_s (threads 0..255)
    if (tid < 256) {
        float4 s0 = swp[0][tid], s1 = swp[1][tid], s2 = swp[2][tid], s3 = swp[3][tid];
        float4 t0 = tp[0][tid],  t1 = tp[1][tid],  t2 = tp[2][tid],  t3 = tp[3][tid];
        float4 s = make_float4(s0.x+s1.x+s2.x+s3.x, s0.y+s1.y+s2.y+s3.y,
                               s0.z+s1.z+s2.z+s3.z, s0.w+s1.w+s2.w+s3.w);
        float4 t = make_float4(t0.x+t1.x+t2.x+t3.x, t0.y+t1.y+t2.y+t3.y,
                               t0.z+t1.z+t2.z+t3.z, t0.w+t1.w+t2.w+t3.w);
        ((float4*)SW_s)[tid] = s;   // tid = g*128 + d4 maps to SW_s[g*512 + d4*4]
        ((float4*)T_s)[tid]  = t;
    }
    __syncthreads();

    const bool mask_is_i32 = (nonzero_offbyte == 0);
    const int warp = tid >> 5;
    const int lane = tid & 31;

    // ---- Phase 2 (L1): logits[n,g]; 72 warp-tasks / 32 warps ----
    for (int p = warp; p < Nq * Gq; p += 32) {
        const int n  = p >> 1;
        const int gg = p & 1;
        const float4* __restrict__ on4 = obj4 + n * D4q;
        const float4* __restrict__ sw4 = (const float4*)(SW_s + gg * Dq);
        const float4* __restrict__ tg4 = (const float4*)(T_s  + gg * Dq);
        float acc = 0.f;
        #pragma unroll
        for (int k = 0; k < 4; k++) {
            const int i = k * 32 + lane;
            float4 o  = __ldg(on4 + i);
            float4 s  = sw4[i];
            float4 tt = tg4[i];
            acc = fmaf(o.x, fmaf(o.x, s.x, -tt.x), acc);
            acc = fmaf(o.y, fmaf(o.y, s.y, -tt.y), acc);
            acc = fmaf(o.z, fmaf(o.z, s.z, -tt.z), acc);
            acc = fmaf(o.w, fmaf(o.w, s.w, -tt.w), acc);
        }
        #pragma unroll
        for (int off = 16; off > 0; off >>= 1)
            acc += __shfl_down_sync(0xffffffffu, acc, off);
        if (lane == 0) logit_s[p] = acc + __ldg(bias + gg);
    }
    __syncthreads();

    // ---- Phase 3: masked softmax over n; warp 0 -> g=0, warp 16 -> g=1 ----
    if ((warp & 15) == 0) {
        const int gg = warp >> 4;
        const int n0 = lane, n1 = lane + 32;
        bool v0 = false, v1 = false;
        if (mask_is_i32) {
            const int* mi = (const int*)mask_bytes;
            if (n0 < Nq) v0 = mi[b * Nq + n0] != 0;
            if (n1 < Nq) v1 = mi[b * Nq + n1] != 0;
        } else {
            if (n0 < Nq) v0 = mask_bytes[b * Nq + n0] != 0;
            if (n1 < Nq) v1 = mask_bytes[b * Nq + n1] != 0;
        }
        float x0 = -1e30f, x1 = -1e30f;
        if (n0 < Nq) x0 = v0 ? logit_s[n0 * Gq + gg] : NEGV;
        if (n1 < Nq) x1 = v1 ? logit_s[n1 * Gq + gg] : NEGV;
        float mx = fmaxf(x0, x1);
        #pragma unroll
        for (int off = 16; off > 0; off >>= 1)
            mx = fmaxf(mx, __shfl_xor_sync(0xffffffffu, mx, off));
        float e0 = (n0 < Nq) ? __expf(x0 - mx) : 0.f;
        float e1 = (n1 < Nq) ? __expf(x1 - mx) : 0.f;
        float s = e0 + e1;
        #pragma unroll
        for (int off = 16; off > 0; off >>= 1)
            s += __shfl_xor_sync(0xffffffffu, s, off);
        const float inv = 1.f / s;
        if (n0 < Nq) weight_s[n0 * Gq + gg] = e0 * inv;
        if (n1 < Nq) weight_s[n1 * Gq + gg] = e1 * inv;
    }
    __syncthreads();

    // ---- Phase 4 (L1): out[b, g*D+d] = sum_n weight[n,g] * obj[n,d] ----
    {
        const int g = tid >> 9;
        const int d = tid & 511;
        float acc = 0.f;
        #pragma unroll
        for (int n = 0; n < Nq; n++)
            acc = fmaf(weight_s[n * Gq + g], __ldg(objb + n * Dq + d), acc);
        out[(size_t)b * (Gq * Dq) + g * Dq + d] = acc;
    }
}

extern "C" void kernel_launch(void* const* d_in, const int* in_sizes, int n_in,
                              void* d_out, int out_size) {
    const float*         obj  = (const float*)d_in[0];         // [128, 36, 512]
    const float*         W    = (const float*)d_in[1];         // [2, 36*512]
    const float*         bias = (const float*)d_in[2];         // [2]
    const unsigned char* mask = (const unsigned char*)d_in[3]; // [128, 36]
    float* out = (float*)d_out;                                // [128, 1024]

    qgen_attn_kernel<<<Bq, 1024>>>(obj, W, bias, mask, out);
}

// round 5
// speedup vs baseline: 1.0029x; 1.0029x over previous
#include <cuda_runtime.h>
#include <cuda_bf16.h>

// Problem constants (from reference)
#define Bq 128
#define Nq 36
#define Dq 512
#define D4q 128          // Dq/4
#define Gq 2
#define NDq (Nq * Dq)
#define NEGV -1e10f

// One block per (batch, glimpse): grid 256, 512 threads (16 warps), 2 CTAs/SM.
// logits factorization:
//   logits[b,n,g] = sum_d o[n,d]^2 * SW[g,d] - sum_d o[n,d] * T[b,g,d]
//   SW[g,d] = sum_m W[g,m,d],  T[b,g,d] = sum_m W[g,m,d]*o[b,m,d]
__global__ __launch_bounds__(512, 2)
void qgen_attn_kernel(const float* __restrict__ obj,   // [B, N, D]
                      const float* __restrict__ W,     // [G, N*D]
                      const float* __restrict__ bias,  // [G]
                      const unsigned char* __restrict__ mask_bytes, // [B,N]
                      float* __restrict__ out)         // [B, G*D]
{
    __shared__ __align__(16) float4 swp[4][D4q];    // 8 KB partials
    __shared__ __align__(16) float4 tpart[4][D4q];  // 8 KB partials
    __shared__ __align__(16) float  T_s[Dq];        // 2 KB
    __shared__ __align__(16) float  SW_s[Dq];       // 2 KB
    __shared__ __align__(16) float4 op4[4][D4q];    // 8 KB phase-4 partials
    __shared__ float logit_s[Nq];
    __shared__ float weight_s[Nq];
    __shared__ int   nonzero_offbyte;

    const int bg  = blockIdx.x;
    const int b   = bg >> 1;          // batch
    const int g   = bg & 1;           // glimpse
    const int tid = threadIdx.x;      // 0..511

    if (tid == 0) nonzero_offbyte = 0;
    __syncthreads();

    // ---- Mask dtype detection (int32 => all bytes at offset%4!=0 are zero) ----
    if (tid < 256 && (tid & 3) != 0) {
        if (mask_bytes[tid] != 0) atomicOr(&nonzero_offbyte, 1);
    }

    const float4* __restrict__ obj4 = (const float4*)(obj + (size_t)b * NDq); // [N][D4]
    const float4* __restrict__ W4   = (const float4*)(W + (size_t)g * NDq);   // [N][D4]

    const int d4 = tid & 127;         // 0..127
    const int sl = tid >> 7;          // 0..3 slice

    // ---- Phase 1 (DRAM): SW/T partials over 9 m's per slice, all float4 ----
    {
        float4 sw = make_float4(0.f, 0.f, 0.f, 0.f);
        float4 tt = make_float4(0.f, 0.f, 0.f, 0.f);
        #pragma unroll
        for (int j = 0; j < 9; j++) {
            const int m = sl * 9 + j;
            float4 w = __ldg(W4   + m * D4q + d4);
            float4 o = __ldg(obj4 + m * D4q + d4);
            sw.x += w.x; sw.y += w.y; sw.z += w.z; sw.w += w.w;
            tt.x = fmaf(w.x, o.x, tt.x);
            tt.y = fmaf(w.y, o.y, tt.y);
            tt.z = fmaf(w.z, o.z, tt.z);
            tt.w = fmaf(w.w, o.w, tt.w);
        }
        swp[sl][d4]   = sw;
        tpart[sl][d4] = tt;
    }
    __syncthreads();

    if (tid < 128) {
        float4 s0 = swp[0][tid], s1 = swp[1][tid], s2 = swp[2][tid], s3 = swp[3][tid];
        float4 t0 = tpart[0][tid], t1 = tpart[1][tid], t2 = tpart[2][tid], t3 = tpart[3][tid];
        ((float4*)SW_s)[tid] = make_float4(s0.x+s1.x+s2.x+s3.x, s0.y+s1.y+s2.y+s3.y,
                                           s0.z+s1.z+s2.z+s3.z, s0.w+s1.w+s2.w+s3.w);
        ((float4*)T_s)[tid]  = make_float4(t0.x+t1.x+t2.x+t3.x, t0.y+t1.y+t2.y+t3.y,
                                           t0.z+t1.z+t2.z+t3.z, t0.w+t1.w+t2.w+t3.w);
    }
    __syncthreads();

    const bool mask_is_i32 = (nonzero_offbyte == 0);
    const int warp = tid >> 5;
    const int lane = tid & 31;

    // ---- Phase 2 (L1/L2): logits[n]; 36 warp-tasks / 16 warps ----
    for (int n = warp; n < Nq; n += 16) {
        const float4* __restrict__ on4 = obj4 + n * D4q;
        const float4* __restrict__ sw4 = (const float4*)SW_s;
        const float4* __restrict__ tg4 = (const float4*)T_s;
        float acc = 0.f;
        #pragma unroll
        for (int k = 0; k < 4; k++) {
            const int i = k * 32 + lane;
            float4 o  = __ldg(on4 + i);
            float4 s  = sw4[i];
            float4 tt = tg4[i];
            acc = fmaf(o.x, fmaf(o.x, s.x, -tt.x), acc);
            acc = fmaf(o.y, fmaf(o.y, s.y, -tt.y), acc);
            acc = fmaf(o.z, fmaf(o.z, s.z, -tt.z), acc);
            acc = fmaf(o.w, fmaf(o.w, s.w, -tt.w), acc);
        }
        #pragma unroll
        for (int off = 16; off > 0; off >>= 1)
            acc += __shfl_down_sync(0xffffffffu, acc, off);
        if (lane == 0) logit_s[n] = acc + __ldg(bias + g);
    }
    __syncthreads();

    // ---- Phase 3: masked softmax over n (warp 0) ----
    if (warp == 0) {
        const int n0 = lane, n1 = lane + 32;
        bool v0 = false, v1 = false;
        if (mask_is_i32) {
            const int* mi = (const int*)mask_bytes;
            v0 = mi[b * Nq + n0] != 0;
            if (n1 < Nq) v1 = mi[b * Nq + n1] != 0;
        } else {
            v0 = mask_bytes[b * Nq + n0] != 0;
            if (n1 < Nq) v1 = mask_bytes[b * Nq + n1] != 0;
        }
        float x0 = v0 ? logit_s[n0] : NEGV;
        float x1 = -1e30f;
        if (n1 < Nq) x1 = v1 ? logit_s[n1] : NEGV;
        float mx = fmaxf(x0, x1);
        #pragma unroll
        for (int off = 16; off > 0; off >>= 1)
            mx = fmaxf(mx, __shfl_xor_sync(0xffffffffu, mx, off));
        float e0 = __expf(x0 - mx);
        float e1 = (n1 < Nq) ? __expf(x1 - mx) : 0.f;
        float s = e0 + e1;
        #pragma unroll
        for (int off = 16; off > 0; off >>= 1)
            s += __shfl_xor_sync(0xffffffffu, s, off);
        const float inv = 1.f / s;
        weight_s[n0] = e0 * inv;
        if (n1 < Nq) weight_s[n1] = e1 * inv;
    }
    __syncthreads();

    // ---- Phase 4 (L1/L2): out[b, g*D + d] = sum_n weight[n] * obj[n,d] ----
    {
        float4 acc = make_float4(0.f, 0.f, 0.f, 0.f);
        #pragma unroll
        for (int j = 0; j < 9; j++) {
            const int n = sl * 9 + j;
            const float wn = weight_s[n];
            float4 o = __ldg(obj4 + n * D4q + d4);
            acc.x = fmaf(wn, o.x, acc.x);
            acc.y = fmaf(wn, o.y, acc.y);
            acc.z = fmaf(wn, o.z, acc.z);
            acc.w = fmaf(wn, o.w, acc.w);
        }
        op4[sl][d4] = acc;
    }
    __syncthreads();

    if (tid < 128) {
        float4 a0 = op4[0][tid], a1 = op4[1][tid], a2 = op4[2][tid], a3 = op4[3][tid];
        float4 r = make_float4(a0.x+a1.x+a2.x+a3.x, a0.y+a1.y+a2.y+a3.y,
                               a0.z+a1.z+a2.z+a3.z, a0.w+a1.w+a2.w+a3.w);
        ((float4*)(out + (size_t)b * (Gq * Dq) + g * Dq))[tid] = r;
    }
}

extern "C" void kernel_launch(void* const* d_in, const int* in_sizes, int n_in,
                              void* d_out, int out_size) {
    const float*         obj  = (const float*)d_in[0];         // [128, 36, 512]
    const float*         W    = (const float*)d_in[1];         // [2, 36*512]
    const float*         bias = (const float*)d_in[2];         // [2]
    const unsigned char* mask = (const unsigned char*)d_in[3]; // [128, 36]
    float* out = (float*)d_out;                                // [128, 1024]

    qgen_attn_kernel<<<Bq * Gq, 512>>>(obj, W, bias, mask, out);
}